// round 16
// baseline (speedup 1.0000x reference)
#include <cuda_runtime.h>
#include <math.h>

// Problem constants (fixed by the reference)
#define BB    4096
#define AA    3
#define HH    13
#define WW    13
#define CC    5
#define NT    32
#define CH    (5 + CC)          // 10 channels per anchor
#define HW    (HH * WW)         // 169
#define NCELL (AA * HW)         // 507

#define TPB   256               // 8 warps per CTA, one batch per warp
#define WPB   8
#define NITW  16                // ceil(507/32) cells per lane

// Per-batch partial results, SoA for coalesced final reduce.
__device__ float g_obj[BB];
__device__ float g_bbox[BB];
__device__ float g_cls[BB];
__device__ unsigned int g_done = 0;   // last-block counter; reset by last block

__device__ __forceinline__ float softplus_fast(float x) {
    // softplus(x) = max(x,0) + log(1+exp(-|x|)); fast-math (abs err < 1e-7)
    return fmaxf(x, 0.0f) + __logf(1.0f + __expf(-fabsf(x)));
}

__global__ void __launch_bounds__(TPB)
sgs_loss_fused(const float* __restrict__ pred,
               const float* __restrict__ tboxes,
               const long long* __restrict__ tlabels,
               const float* __restrict__ anchors,
               float* __restrict__ out, int B)
{
    // Per-warp private regions; 512-padded rows for alignment.
    __shared__ int   s_win[WPB][512];
    __shared__ int   s_win_cls[WPB][512];
    __shared__ float s_tbox[WPB][NT][4];
    __shared__ int   s_lab[WPB][NT];
    __shared__ int   s_islast;
    __shared__ float s_red[8][3];

    const int wid  = threadIdx.x >> 5;
    const int lane = threadIdx.x & 31;
    const int b    = blockIdx.x * WPB + wid;
    const bool active = (b < B);              // no early return: all warps reach barriers

    if (active) {
        int*   win  = s_win[wid];
        int*   winc = s_win_cls[wid];
        const float* pb = pred + (size_t)b * (AA * CH * HW);

        // ---- init winner maps + prefetch obj logits (16 independent LDGs) ----
        float po[NITW];
        #pragma unroll
        for (int it = 0; it < NITW; it++) {
            int c = lane + it * 32;
            if (c < NCELL) { win[c] = -1; winc[c] = -1; }
            int a = c / HW, hw = c - a * HW;
            po[it] = (c < NCELL) ? pb[a * CH * HW + hw] : 0.0f;
        }
        __syncwarp();

        // ---- per-target processing (one target per lane; full warp active) ----
        {
            float4 box = ((const float4*)tboxes)[b * NT + lane];
            float cx = box.x, cy = box.y, w = box.z, h = box.w;
            bool valid = (cx > 0.0f) && (cx < 1.0f) && (cy > 0.0f) && (cy < 1.0f)
                      && (w > 0.0f) && (h > 0.0f);
            float ws = valid ? w : 1.0f;
            float hs = valid ? h : 1.0f;
            int gx = (int)(cx * (float)WW); gx = min(max(gx, 0), WW - 1);
            int gy = (int)(cy * (float)HH); gy = min(max(gy, 0), HH - 1);

            // argmax IoU over anchors (first occurrence on ties)
            int   besta = 0;
            float bestiou = -1.0f, baw = 1.0f, bah = 1.0f;
            #pragma unroll
            for (int a = 0; a < AA; a++) {
                float aw = anchors[a * 2 + 0];
                float ah = anchors[a * 2 + 1];
                float inter = fminf(ws, aw) * fminf(hs, ah);
                float iou = inter / (ws * hs + aw * ah - inter);
                if (iou > bestiou) { bestiou = iou; besta = a; baw = aw; bah = ah; }
            }

            s_tbox[wid][lane][0] = cx * (float)WW - (float)gx;
            s_tbox[wid][lane][1] = cy * (float)HH - (float)gy;
            s_tbox[wid][lane][2] = __logf(ws / baw + 1e-16f);
            s_tbox[wid][lane][3] = __logf(hs / bah + 1e-16f);

            long long lb = tlabels[b * NT + lane];
            bool labok = (lb >= 0) && (lb < (long long)CC);
            long long lc = lb < 0 ? 0 : (lb > (long long)(CC - 1) ? (long long)(CC - 1) : lb);
            s_lab[wid][lane] = (int)lc;

            if (valid) {
                int cell = besta * HW + gy * WW + gx;
                atomicMax(&win[cell], lane);           // last-update-wins
                if (labok) atomicMax(&winc[cell], lane);
            }
        }
        __syncwarp();

        // ---- main loss over 507 cells (obj logits already in registers) ----
        float neg = 0.0f, pos = 0.0f, bsum = 0.0f, csum = 0.0f;
        int   cnt = 0;

        #pragma unroll
        for (int it = 0; it < NITW; it++) {
            int cidx = lane + it * 32;
            if (cidx >= NCELL) break;

            float sp = softplus_fast(po[it]);   // bce(x,0)=sp ; bce(x,1)=sp-x
            int wg = win[cidx];
            if (wg < 0) {
                neg += sp;
            } else {
                pos += sp - po[it];
                cnt++;
                int a  = cidx / HW;
                int hw = cidx - a * HW;
                const float* cp = pb + a * CH * HW + hw;
                #pragma unroll
                for (int j = 0; j < 4; j++) {
                    float d = cp[(1 + j) * HW] - s_tbox[wid][wg][j];
                    bsum += d * d;
                }
                int wc = winc[cidx];
                int lb = (wc >= 0) ? s_lab[wid][wc] : -1;
                #pragma unroll
                for (int c = 0; c < CC; c++) {
                    float pc = cp[(5 + c) * HW];
                    csum += softplus_fast(pc) - ((c == lb) ? pc : 0.0f);
                }
            }
        }

        // ---- warp reduction; lane 0 writes per-batch partials ----
        float v[5] = {neg, pos, bsum, csum, (float)cnt};
        #pragma unroll
        for (int o = 16; o > 0; o >>= 1) {
            #pragma unroll
            for (int k = 0; k < 5; k++) v[k] += __shfl_down_sync(0xFFFFFFFFu, v[k], o);
        }

        if (lane == 0) {
            float npos = v[4];
            float pw = ((float)NCELL - npos) / (npos + 1e-16f);
            float obj_b  = (v[0] + pw * v[1]) / (float)NCELL;
            float bbox_b = (npos > 0.0f) ? v[2] / (4.0f * npos + 1e-30f) : 0.0f;
            float cls_b  = (npos > 0.0f) ? v[3] / ((float)CC * npos + 1e-30f) : 0.0f;
            g_obj[b]  = obj_b;
            g_bbox[b] = bbox_b;
            g_cls[b]  = cls_b;
        }
    }

    // ---- last-block final reduction (threadFenceReduction pattern) ----
    __threadfence();                    // order partial-result stores before counter
    __syncthreads();
    if (threadIdx.x == 0) {
        unsigned int t = atomicAdd(&g_done, 1u);
        s_islast = (t == (unsigned int)(gridDim.x - 1)) ? 1 : 0;
    }
    __syncthreads();
    if (!s_islast) return;

    // Last CTA: 256 threads sum B=4096 partials per array (L2-hot, __ldcg fresh).
    const int tid = threadIdx.x;
    const int nvec = B >> 2;
    float o = 0.0f, bb = 0.0f, cl = 0.0f;
    for (int i = tid; i < nvec; i += TPB) {
        float4 vo = __ldcg(((const float4*)g_obj) + i);
        float4 vb = __ldcg(((const float4*)g_bbox) + i);
        float4 vc = __ldcg(((const float4*)g_cls) + i);
        o  += (vo.x + vo.y) + (vo.z + vo.w);
        bb += (vb.x + vb.y) + (vb.z + vb.w);
        cl += (vc.x + vc.y) + (vc.z + vc.w);
    }
    for (int i = (nvec << 2) + tid; i < B; i += TPB) {    // tail (empty for B=4096)
        o += __ldcg(g_obj + i); bb += __ldcg(g_bbox + i); cl += __ldcg(g_cls + i);
    }

    #pragma unroll
    for (int off = 16; off > 0; off >>= 1) {
        o  += __shfl_down_sync(0xFFFFFFFFu, o,  off);
        bb += __shfl_down_sync(0xFFFFFFFFu, bb, off);
        cl += __shfl_down_sync(0xFFFFFFFFu, cl, off);
    }
    if (lane == 0) { s_red[wid][0] = o; s_red[wid][1] = bb; s_red[wid][2] = cl; }
    __syncthreads();

    if (tid == 0) {
        double ro = 0.0, rb = 0.0, rc = 0.0;
        #pragma unroll
        for (int w2 = 0; w2 < 8; w2++) {
            ro += (double)s_red[w2][0];
            rb += (double)s_red[w2][1];
            rc += (double)s_red[w2][2];
        }
        float objf  = (float)(ro / (double)B);
        float bboxf = (float)(rb / (double)B);
        float clsf  = (float)(rc / (double)B);
        out[0] = 2.0f * objf + 5.0f * bboxf + 2.0f * clsf;
        out[1] = objf;
        out[2] = bboxf;
        out[3] = clsf;
        g_done = 0;   // reset for next graph replay
    }
}

extern "C" void kernel_launch(void* const* d_in, const int* in_sizes, int n_in,
                              void* d_out, int out_size)
{
    const float*     pred    = (const float*)d_in[0];
    const float*     tboxes  = (const float*)d_in[1];
    const long long* tlabels = (const long long*)d_in[2];
    const float*     anchors = (const float*)d_in[3];
    float*           out     = (float*)d_out;

    int B = in_sizes[0] / (AA * CH * HW);
    if (B > BB) B = BB;

    int nblk = (B + WPB - 1) / WPB;
    sgs_loss_fused<<<nblk, TPB>>>(pred, tboxes, tlabels, anchors, out, B);
}

// round 17
// speedup vs baseline: 1.0171x; 1.0171x over previous
#include <cuda_runtime.h>
#include <math.h>

// Problem constants (fixed by the reference)
#define BB    4096
#define AA    3
#define HH    13
#define WW    13
#define CC    5
#define NT    32
#define CH    (5 + CC)          // 10 channels per anchor
#define HW    (HH * WW)         // 169
#define NCELL (AA * HW)         // 507

#define TPB   256               // 8 warps per CTA, one batch per warp
#define WPB   8
#define NITW  16                // ceil(507/32) cells per lane

// Per-batch partial results, SoA for coalesced reduce.
__device__ float g_obj[BB];
__device__ float g_bbox[BB];
__device__ float g_cls[BB];

__device__ __forceinline__ float softplus_fast(float x) {
    // softplus(x) = max(x,0) + log(1+exp(-|x|)); fast-math (abs err < 1e-7)
    return fmaxf(x, 0.0f) + __logf(1.0f + __expf(-fabsf(x)));
}

__global__ void __launch_bounds__(TPB)
sgs_loss_per_batch(const float* __restrict__ pred,
                   const float* __restrict__ tboxes,
                   const long long* __restrict__ tlabels,
                   const float* __restrict__ anchors,
                   int B)
{
    // Per-warp private regions; 512-padded rows for alignment.
    __shared__ int   s_win[WPB][512];
    __shared__ int   s_win_cls[WPB][512];
    __shared__ float s_tbox[WPB][NT][4];
    __shared__ int   s_lab[WPB][NT];

    const int wid  = threadIdx.x >> 5;
    const int lane = threadIdx.x & 31;
    const int b    = blockIdx.x * WPB + wid;
    if (b >= B) return;                       // whole-warp uniform exit

    int*   win  = s_win[wid];
    int*   winc = s_win_cls[wid];
    const float* pb = pred + (size_t)b * (AA * CH * HW);

    // ---- init winner maps + prefetch obj logits (16 independent LDGs) ----
    float po[NITW];
    #pragma unroll
    for (int it = 0; it < NITW; it++) {
        int c = lane + it * 32;
        if (c < NCELL) { win[c] = -1; winc[c] = -1; }
        int a = c / HW, hw = c - a * HW;
        po[it] = (c < NCELL) ? pb[a * CH * HW + hw] : 0.0f;
    }
    __syncwarp();

    // ---- per-target processing (one target per lane; full warp active) ----
    {
        float4 box = ((const float4*)tboxes)[b * NT + lane];
        float cx = box.x, cy = box.y, w = box.z, h = box.w;
        bool valid = (cx > 0.0f) && (cx < 1.0f) && (cy > 0.0f) && (cy < 1.0f)
                  && (w > 0.0f) && (h > 0.0f);
        float ws = valid ? w : 1.0f;
        float hs = valid ? h : 1.0f;
        int gx = (int)(cx * (float)WW); gx = min(max(gx, 0), WW - 1);
        int gy = (int)(cy * (float)HH); gy = min(max(gy, 0), HH - 1);

        // argmax IoU over anchors (first occurrence on ties, matching jnp.argmax)
        int   besta = 0;
        float bestiou = -1.0f, baw = 1.0f, bah = 1.0f;
        #pragma unroll
        for (int a = 0; a < AA; a++) {
            float aw = anchors[a * 2 + 0];
            float ah = anchors[a * 2 + 1];
            float inter = fminf(ws, aw) * fminf(hs, ah);
            float iou = inter / (ws * hs + aw * ah - inter);
            if (iou > bestiou) { bestiou = iou; besta = a; baw = aw; bah = ah; }
        }

        s_tbox[wid][lane][0] = cx * (float)WW - (float)gx;
        s_tbox[wid][lane][1] = cy * (float)HH - (float)gy;
        s_tbox[wid][lane][2] = __logf(ws / baw + 1e-16f);   // feeds squared loss
        s_tbox[wid][lane][3] = __logf(hs / bah + 1e-16f);

        long long lb = tlabels[b * NT + lane];
        bool labok = (lb >= 0) && (lb < (long long)CC);
        long long lc = lb < 0 ? 0 : (lb > (long long)(CC - 1) ? (long long)(CC - 1) : lb);
        s_lab[wid][lane] = (int)lc;

        if (valid) {
            int cell = besta * HW + gy * WW + gx;
            atomicMax(&win[cell], lane);           // last-update-wins
            if (labok) atomicMax(&winc[cell], lane);
        }
    }
    __syncwarp();

    // ---- main loss over 507 cells (obj logits already in registers) ----
    float neg = 0.0f, pos = 0.0f, bsum = 0.0f, csum = 0.0f;
    int   cnt = 0;

    #pragma unroll
    for (int it = 0; it < NITW; it++) {
        int cidx = lane + it * 32;
        if (cidx >= NCELL) break;

        float sp = softplus_fast(po[it]);   // bce(x,0)=sp ; bce(x,1)=sp-x
        int wg = win[cidx];
        if (wg < 0) {
            neg += sp;
        } else {
            pos += sp - po[it];
            cnt++;
            int a  = cidx / HW;
            int hw = cidx - a * HW;
            const float* cp = pb + a * CH * HW + hw;
            #pragma unroll
            for (int j = 0; j < 4; j++) {
                float d = cp[(1 + j) * HW] - s_tbox[wid][wg][j];
                bsum += d * d;
            }
            int wc = winc[cidx];
            int lb = (wc >= 0) ? s_lab[wid][wc] : -1;
            #pragma unroll
            for (int c = 0; c < CC; c++) {
                float pc = cp[(5 + c) * HW];
                csum += softplus_fast(pc) - ((c == lb) ? pc : 0.0f);
            }
        }
    }

    // ---- warp reduction of {neg, pos, bsum, csum, cnt}; lane 0 writes ----
    float v[5] = {neg, pos, bsum, csum, (float)cnt};
    #pragma unroll
    for (int o = 16; o > 0; o >>= 1) {
        #pragma unroll
        for (int k = 0; k < 5; k++) v[k] += __shfl_down_sync(0xFFFFFFFFu, v[k], o);
    }

    if (lane == 0) {
        float npos = v[4];
        float pw = ((float)NCELL - npos) / (npos + 1e-16f);
        float obj_b  = (v[0] + pw * v[1]) / (float)NCELL;
        float bbox_b = (npos > 0.0f) ? v[2] / (4.0f * npos + 1e-30f) : 0.0f;
        float cls_b  = (npos > 0.0f) ? v[3] / ((float)CC * npos + 1e-30f) : 0.0f;
        g_obj[b]  = obj_b;
        g_bbox[b] = bbox_b;
        g_cls[b]  = cls_b;
    }
}

// 1024 threads: one float4 per thread per array for B=4096.
// PDL secondary: pre-launched while kernel 1 runs; griddepcontrol.wait blocks
// on-device until the primary grid completes (partials then visible).
__global__ void __launch_bounds__(1024)
sgs_loss_reduce(float* __restrict__ out, int B)
{
    asm volatile("griddepcontrol.wait;" ::: "memory");

    __shared__ float s_red[32][3];
    const int tid = threadIdx.x;
    const int nvec = B >> 2;               // 1024 for B=4096

    float o = 0.0f, bb = 0.0f, cl = 0.0f;
    for (int i = tid; i < nvec; i += 1024) {
        float4 vo = ((const float4*)g_obj)[i];
        float4 vb = ((const float4*)g_bbox)[i];
        float4 vc = ((const float4*)g_cls)[i];
        o  += (vo.x + vo.y) + (vo.z + vo.w);
        bb += (vb.x + vb.y) + (vb.z + vb.w);
        cl += (vc.x + vc.y) + (vc.z + vc.w);
    }
    for (int i = (nvec << 2) + tid; i < B; i += 1024) {   // tail (empty for B=4096)
        o += g_obj[i]; bb += g_bbox[i]; cl += g_cls[i];
    }

    #pragma unroll
    for (int off = 16; off > 0; off >>= 1) {
        o  += __shfl_down_sync(0xFFFFFFFFu, o,  off);
        bb += __shfl_down_sync(0xFFFFFFFFu, bb, off);
        cl += __shfl_down_sync(0xFFFFFFFFu, cl, off);
    }
    int wid = tid >> 5, lid = tid & 31;
    if (lid == 0) { s_red[wid][0] = o; s_red[wid][1] = bb; s_red[wid][2] = cl; }
    __syncthreads();

    if (tid == 0) {
        double ro = 0.0, rb = 0.0, rc = 0.0;
        #pragma unroll
        for (int w2 = 0; w2 < 32; w2++) {
            ro += (double)s_red[w2][0];
            rb += (double)s_red[w2][1];
            rc += (double)s_red[w2][2];
        }
        float obj  = (float)(ro / (double)B);
        float bbox = (float)(rb / (double)B);
        float cls  = (float)(rc / (double)B);
        out[0] = 2.0f * obj + 5.0f * bbox + 2.0f * cls;
        out[1] = obj;
        out[2] = bbox;
        out[3] = cls;
    }
}

extern "C" void kernel_launch(void* const* d_in, const int* in_sizes, int n_in,
                              void* d_out, int out_size)
{
    const float*     pred    = (const float*)d_in[0];
    const float*     tboxes  = (const float*)d_in[1];
    const long long* tlabels = (const long long*)d_in[2];
    const float*     anchors = (const float*)d_in[3];
    float*           out     = (float*)d_out;

    int B = in_sizes[0] / (AA * CH * HW);
    if (B > BB) B = BB;

    int nblk = (B + WPB - 1) / WPB;
    sgs_loss_per_batch<<<nblk, TPB>>>(pred, tboxes, tlabels, anchors, B);

    // Reduce with programmatic dependent launch: launch overlaps kernel 1.
    cudaLaunchConfig_t cfg = {};
    cfg.gridDim  = dim3(1, 1, 1);
    cfg.blockDim = dim3(1024, 1, 1);
    cfg.dynamicSmemBytes = 0;
    cfg.stream = 0;   // same (legacy) stream the harness captures
    cudaLaunchAttribute attrs[1];
    attrs[0].id = cudaLaunchAttributeProgrammaticStreamSerialization;
    attrs[0].val.programmaticStreamSerializationAllowed = 1;
    cfg.attrs = attrs;
    cfg.numAttrs = 1;
    cudaLaunchKernelEx(&cfg, sgs_loss_reduce, out, B);
}